// round 1
// baseline (speedup 1.0000x reference)
#include <cuda_runtime.h>
#include <cuda_bf16.h>
#include <cstdint>
#include <cstdio>

// ---------------------------------------------------------------------------
// Problem constants
// ---------------------------------------------------------------------------
#define NB 1024
static const int D_TOT = 267696;

// per-layer weight offsets (flat, in elements) and shapes
static const int H_OFFS[20] = {0,432,2736,5040,7344,9648,11952,14256,18864,28080,
                               37296,46512,55728,64944,83376,120240,157104,193968,230832,267696};

__constant__ int c_OFFS[20] = {0,432,2736,5040,7344,9648,11952,14256,18864,28080,
                               37296,46512,55728,64944,83376,120240,157104,193968,230832,267696};
__constant__ int c_CIN[19]  = {3,16,16,16,16,16,16,16,32,32,32,32,32,32,64,64,64,64,64};
__constant__ int c_COUT[19] = {16,16,16,16,16,16,16,32,32,32,32,32,32,64,64,64,64,64,64};

// ---------------------------------------------------------------------------
// Device scratch (no allocations allowed -> __device__ globals)
// ---------------------------------------------------------------------------
#define BUF_ELEMS (1024*16*32*32)   // 16.78M floats, largest activation
__device__ float  g_bufA[BUF_ELEMS];
__device__ float  g_bufB[BUF_ELEMS];
__device__ float  g_bufC[BUF_ELEMS];
__device__ float  g_w[267696];       // transposed per-layer: [cin][3x3][cout]
__device__ double g_stats[19*64*2];  // per layer, per channel: sum, sumsq

// ---------------------------------------------------------------------------
// Zero the BN stat accumulators (start of every graph replay)
// ---------------------------------------------------------------------------
__global__ void zstats_k(double* __restrict__ st) {
    int i = blockIdx.x * blockDim.x + threadIdx.x;
    if (i < 19*64*2) st[i] = 0.0;
}

// ---------------------------------------------------------------------------
// Reconstruct w_flat = origin + new_param @ P, then scatter into transposed
// per-layer layout [cin][ky*3+kx][cout] so conv blocks can stage weights with
// a contiguous copy and read them with LDS.128.
// ---------------------------------------------------------------------------
__global__ void wbuild_k(const float* __restrict__ ow, const float* __restrict__ P,
                         const float* __restrict__ npar, float* __restrict__ wt) {
    __shared__ float s_np[40];
    if (threadIdx.x < 40) s_np[threadIdx.x] = npar[threadIdx.x];
    __syncthreads();
    int d = blockIdx.x * blockDim.x + threadIdx.x;
    if (d >= D_TOT) return;
    float a = ow[d];
#pragma unroll
    for (int j = 0; j < 40; j++)
        a = fmaf(s_np[j], P[(size_t)j * D_TOT + d], a);
    // locate layer
    int l = 0;
    while (d >= c_OFFS[l+1]) l++;
    int r    = d - c_OFFS[l];
    int cin  = c_CIN[l];
    int cout = c_COUT[l];
    int oc   = r / (cin * 9);
    int rem  = r - oc * cin * 9;       // = ic*9 + k
    wt[c_OFFS[l] + rem * cout + oc] = a;
}

// ---------------------------------------------------------------------------
// Direct 3x3 conv, one image per block, 256 threads.
//   - input tile (padded) staged in smem, optional BN+ReLU applied on load
//   - weights staged in smem in [icr][k][oc] layout (LDS.128 reads)
//   - epilogue: write raw conv output + per-channel sum/sumsq block reduction
//     -> one double atomicAdd per (block, channel)
// ---------------------------------------------------------------------------
template<int CIN, int COUT, int HIN, int STRIDE, bool BN_IN>
__global__ void __launch_bounds__(256)
conv3x3_k(const float* __restrict__ in, const float* __restrict__ wt,
          float* __restrict__ out, const double* __restrict__ st_in,
          double* __restrict__ st_out)
{
    constexpr int HOUT   = HIN / STRIDE;
    constexpr int NPOS   = HOUT * HOUT;
    constexpr int PPT    = (NPOS >= 256) ? NPOS / 256 : 1;  // positions / thread
    constexpr int OCG    = (NPOS >= 256) ? 1 : 256 / NPOS;  // oc groups
    constexpr int OCPT   = COUT / OCG;                      // oc / thread
    constexpr int TIN    = HIN + 2;
    constexpr int INTILE = CIN * TIN * TIN;
    constexpr int WCHUNK = (COUT * CIN * 9 * 4 <= 40960) ? CIN : 16;
    constexpr int WTILE  = WCHUNK * 9 * COUT;

    extern __shared__ float sm[];
    float* s_in = sm;
    float* s_w  = sm + INTILE;
    float* s_sc = s_w + WTILE;
    float* s_sh = s_sc + CIN;

    const int tid = threadIdx.x;
    const int n   = blockIdx.x;

    if (BN_IN) {
        if (tid < CIN) {
            const double cnt = 1024.0 * HIN * HIN;
            double m = st_in[tid*2]   / cnt;
            double v = st_in[tid*2+1] / cnt - m * m;
            float rs = rsqrtf((float)v + 1e-5f);
            s_sc[tid] = rs;
            s_sh[tid] = (float)(-m) * rs;
        }
        __syncthreads();
    }

    // stage (padded) input tile, applying BN+ReLU if requested
    const float* inb = in + (size_t)n * CIN * HIN * HIN;
    for (int idx = tid; idx < INTILE; idx += 256) {
        int c  = idx / (TIN * TIN);
        int rr = idx - c * TIN * TIN;
        int iy = rr / TIN - 1;
        int ix = rr - (iy + 1) * TIN - 1;
        float v = 0.f;
        if ((unsigned)iy < (unsigned)HIN && (unsigned)ix < (unsigned)HIN) {
            v = __ldg(&inb[(c * HIN + iy) * HIN + ix]);
            if (BN_IN) v = fmaxf(fmaf(v, s_sc[c], s_sh[c]), 0.f);
        }
        s_in[idx] = v;
    }

    int pos0, ocbase;
    if (OCG == 1) { pos0 = tid;        ocbase = 0; }
    else          { pos0 = tid % NPOS; ocbase = (tid / NPOS) * OCPT; }

    float acc[OCPT][PPT];
#pragma unroll
    for (int o = 0; o < OCPT; o++)
#pragma unroll
        for (int i = 0; i < PPT; i++) acc[o][i] = 0.f;

    for (int ic0 = 0; ic0 < CIN; ic0 += WCHUNK) {
        __syncthreads();   // also covers initial s_in staging
        for (int idx = tid; idx < WTILE; idx += 256)
            s_w[idx] = wt[(size_t)ic0 * 9 * COUT + idx];
        __syncthreads();

#pragma unroll 1
        for (int icr = 0; icr < WCHUNK; icr++) {
            const int ic = ic0 + icr;
#pragma unroll
            for (int k = 0; k < 9; k++) {
                const int ky = k / 3, kx = k % 3;
                float iv[PPT];
#pragma unroll
                for (int i = 0; i < PPT; i++) {
                    int p  = pos0 + i * 256;
                    int oy = p / HOUT, ox = p % HOUT;
                    iv[i] = s_in[(ic * TIN + oy * STRIDE + ky) * TIN + ox * STRIDE + kx];
                }
                const float4* wp =
                    reinterpret_cast<const float4*>(&s_w[(icr * 9 + k) * COUT + ocbase]);
#pragma unroll
                for (int o4 = 0; o4 < OCPT / 4; o4++) {
                    float4 w4 = wp[o4];
#pragma unroll
                    for (int i = 0; i < PPT; i++) {
                        acc[o4*4+0][i] = fmaf(w4.x, iv[i], acc[o4*4+0][i]);
                        acc[o4*4+1][i] = fmaf(w4.y, iv[i], acc[o4*4+1][i]);
                        acc[o4*4+2][i] = fmaf(w4.z, iv[i], acc[o4*4+2][i]);
                        acc[o4*4+3][i] = fmaf(w4.w, iv[i], acc[o4*4+3][i]);
                    }
                }
            }
        }
    }

    // write raw conv output + per-thread partial stats
    const size_t ob = (size_t)n * COUT * NPOS;
    float psum[OCPT], psq[OCPT];
#pragma unroll
    for (int o = 0; o < OCPT; o++) { psum[o] = 0.f; psq[o] = 0.f; }
#pragma unroll
    for (int o = 0; o < OCPT; o++)
#pragma unroll
        for (int i = 0; i < PPT; i++) {
            int p   = pos0 + i * 256;
            float v = acc[o][i];
            out[ob + (size_t)(ocbase + o) * NPOS + p] = v;
            psum[o] += v;
            psq[o]   = fmaf(v, v, psq[o]);
        }

    // warp reduce (all lanes of a warp share the same oc set)
#pragma unroll
    for (int o = 0; o < OCPT; o++) {
#pragma unroll
        for (int s = 16; s; s >>= 1) {
            psum[o] += __shfl_down_sync(0xffffffffu, psum[o], s);
            psq[o]  += __shfl_down_sync(0xffffffffu, psq[o],  s);
        }
    }

    __syncthreads();                 // s_in no longer needed -> reuse as scratch
    float* s_red = sm;               // [8 warps][COUT][2]
    for (int idx = tid; idx < 8 * COUT * 2; idx += 256) s_red[idx] = 0.f;
    __syncthreads();
    const int lane = tid & 31, wid = tid >> 5;
    if (lane == 0) {
#pragma unroll
        for (int o = 0; o < OCPT; o++) {
            s_red[(wid * COUT + ocbase + o) * 2 + 0] = psum[o];
            s_red[(wid * COUT + ocbase + o) * 2 + 1] = psq[o];
        }
    }
    __syncthreads();
    if (tid < COUT) {
        float s = 0.f, q = 0.f;
#pragma unroll
        for (int w8 = 0; w8 < 8; w8++) {
            s += s_red[(w8 * COUT + tid) * 2 + 0];
            q += s_red[(w8 * COUT + tid) * 2 + 1];
        }
        atomicAdd(&st_out[tid * 2 + 0], (double)s);
        atomicAdd(&st_out[tid * 2 + 1], (double)q);
    }
}

// ---------------------------------------------------------------------------
// Residual epilogue: out = relu( bn(h) + shortcut(prev) )
//   MODE 0: no shortcut (layer 0)
//   MODE 1: identity shortcut
//   MODE 2: stride-2 subsample + channel zero-pad shortcut
// ---------------------------------------------------------------------------
template<int C, int H, int MODE, int CPREV>
__global__ void __launch_bounds__(256)
elem_k(const float* __restrict__ h, const double* __restrict__ st,
       const float* __restrict__ prev, float* __restrict__ out)
{
    __shared__ float s_sc[C], s_sh[C];
    if (threadIdx.x < C) {
        const double cnt = 1024.0 * H * H;
        double m = st[threadIdx.x*2]   / cnt;
        double v = st[threadIdx.x*2+1] / cnt - m * m;
        float rs = rsqrtf((float)v + 1e-5f);
        s_sc[threadIdx.x] = rs;
        s_sh[threadIdx.x] = (float)(-m) * rs;
    }
    __syncthreads();

    const int total = 1024 * C * H * H;
    for (int idx = blockIdx.x * blockDim.x + threadIdx.x; idx < total;
         idx += gridDim.x * blockDim.x) {
        int hw = idx % (H * H);
        int c  = (idx / (H * H)) % C;
        int n  = idx / (H * H * C);
        float v = fmaf(h[idx], s_sc[c], s_sh[c]);
        float s = 0.f;
        if (MODE == 1) {
            s = prev[idx];
        } else if (MODE == 2) {
            const int pc = c - (C - CPREV) / 2;
            if (pc >= 0 && pc < CPREV) {
                int y = hw / H, x = hw - y * H;
                s = prev[((size_t)n * CPREV + pc) * (4 * H * H) + (2*y) * (2*H) + 2*x];
            }
        }
        out[idx] = fmaxf(v + s, 0.f);
    }
}

// ---------------------------------------------------------------------------
// Global average pool (8x8) + FC 64->10
// ---------------------------------------------------------------------------
__global__ void __launch_bounds__(64)
poolfc_k(const float* __restrict__ in, const float* __restrict__ Wfc,
         const float* __restrict__ bfc, float* __restrict__ out)
{
    __shared__ float pooled[64];
    const int n = blockIdx.x, t = threadIdx.x;
    const float* p = in + (size_t)n * 64 * 64;
    float s = 0.f;
#pragma unroll
    for (int i = 0; i < 64; i++) s += p[t * 64 + i];
    pooled[t] = s * (1.f / 64.f);
    __syncthreads();
    if (t < 10) {
        float a = bfc[t];
#pragma unroll
        for (int c = 0; c < 64; c++) a = fmaf(Wfc[t * 64 + c], pooled[c], a);
        out[n * 10 + t] = a;
    }
}

// ---------------------------------------------------------------------------
// Host-side smem size helper (must match kernel layout)
// ---------------------------------------------------------------------------
static constexpr int conv_smem(int CIN, int COUT, int HIN) {
    int TIN = HIN + 2;
    int W   = (COUT * CIN * 9 * 4 <= 40960) ? CIN : 16;
    return (CIN * TIN * TIN + W * 9 * COUT + 2 * CIN) * 4;
}

extern "C" void kernel_launch(void* const* d_in, const int* in_sizes, int n_in,
                              void* d_out, int out_size)
{
    (void)in_sizes; (void)n_in; (void)out_size;
    const float* x   = (const float*)d_in[0];
    const float* ow  = (const float*)d_in[1];
    const float* P   = (const float*)d_in[2];
    const float* npar= (const float*)d_in[3];
    const float* Wfc = (const float*)d_in[4];
    const float* bfc = (const float*)d_in[5];
    float* y = (float*)d_out;

    float *A, *B, *C, *w; double* st;
    cudaGetSymbolAddress((void**)&A, g_bufA);
    cudaGetSymbolAddress((void**)&B, g_bufB);
    cudaGetSymbolAddress((void**)&C, g_bufC);
    cudaGetSymbolAddress((void**)&w, g_w);
    cudaGetSymbolAddress((void**)&st, g_stats);

    // opt in to >48KB dynamic smem (idempotent)
    cudaFuncSetAttribute(conv3x3_k< 3,16,32,1,false>, cudaFuncAttributeMaxDynamicSharedMemorySize, conv_smem( 3,16,32));
    cudaFuncSetAttribute(conv3x3_k<16,16,32,1,false>, cudaFuncAttributeMaxDynamicSharedMemorySize, conv_smem(16,16,32));
    cudaFuncSetAttribute(conv3x3_k<16,16,32,1,true >, cudaFuncAttributeMaxDynamicSharedMemorySize, conv_smem(16,16,32));
    cudaFuncSetAttribute(conv3x3_k<16,32,32,2,false>, cudaFuncAttributeMaxDynamicSharedMemorySize, conv_smem(16,32,32));
    cudaFuncSetAttribute(conv3x3_k<32,32,16,1,true >, cudaFuncAttributeMaxDynamicSharedMemorySize, conv_smem(32,32,16));
    cudaFuncSetAttribute(conv3x3_k<32,32,16,1,false>, cudaFuncAttributeMaxDynamicSharedMemorySize, conv_smem(32,32,16));
    cudaFuncSetAttribute(conv3x3_k<32,64,16,2,false>, cudaFuncAttributeMaxDynamicSharedMemorySize, conv_smem(32,64,16));
    cudaFuncSetAttribute(conv3x3_k<64,64, 8,1,true >, cudaFuncAttributeMaxDynamicSharedMemorySize, conv_smem(64,64, 8));
    cudaFuncSetAttribute(conv3x3_k<64,64, 8,1,false>, cudaFuncAttributeMaxDynamicSharedMemorySize, conv_smem(64,64, 8));

    auto ST = [&](int l) { return st + l * 128; };

    zstats_k<<<(19*64*2 + 255)/256, 256>>>(st);
    wbuild_k<<<(D_TOT + 255)/256, 256>>>(ow, P, npar, w);

    // ---- layer 0: out = relu(bn(conv0(x))) -> buffer B ----
    conv3x3_k<3,16,32,1,false><<<NB,256,conv_smem(3,16,32)>>>(x, w + H_OFFS[0], A, nullptr, ST(0));
    elem_k<16,32,0,16><<<4096,256>>>(A, ST(0), nullptr, B);

    float* o  = B;   // current activation
    float* h  = C;   // free
    float* h2 = A;   // free

    // a-conv: o -> h (raw, stats la); b-conv: bn(h)+relu -> h2 (stats lb);
    // elem: relu(bn(h2) + shortcut(o)) -> h; rotate (o,h,h2) = (h,h2,o)
#define ROT() { float* t = o; o = h; h = h2; h2 = t; }

    // ---- stage 1: blocks (1,2) (3,4) (5,6), 16ch @32x32 ----
    for (int b = 0; b < 3; b++) {
        int la = 1 + 2*b, lb = la + 1;
        conv3x3_k<16,16,32,1,false><<<NB,256,conv_smem(16,16,32)>>>(o, w + H_OFFS[la], h,  nullptr, ST(la));
        conv3x3_k<16,16,32,1,true ><<<NB,256,conv_smem(16,16,32)>>>(h, w + H_OFFS[lb], h2, ST(la),  ST(lb));
        elem_k<16,32,1,16><<<4096,256>>>(h2, ST(lb), o, h);
        ROT();
    }

    // ---- block 4: (7,8,2,32)  16->32, 32x32 -> 16x16 ----
    conv3x3_k<16,32,32,2,false><<<NB,256,conv_smem(16,32,32)>>>(o, w + H_OFFS[7], h,  nullptr, ST(7));
    conv3x3_k<32,32,16,1,true ><<<NB,256,conv_smem(32,32,16)>>>(h, w + H_OFFS[8], h2, ST(7),   ST(8));
    elem_k<32,16,2,16><<<4096,256>>>(h2, ST(8), o, h);
    ROT();

    // ---- blocks 5,6: (9,10) (11,12), 32ch @16x16 ----
    for (int b = 0; b < 2; b++) {
        int la = 9 + 2*b, lb = la + 1;
        conv3x3_k<32,32,16,1,false><<<NB,256,conv_smem(32,32,16)>>>(o, w + H_OFFS[la], h,  nullptr, ST(la));
        conv3x3_k<32,32,16,1,true ><<<NB,256,conv_smem(32,32,16)>>>(h, w + H_OFFS[lb], h2, ST(la),  ST(lb));
        elem_k<32,16,1,32><<<4096,256>>>(h2, ST(lb), o, h);
        ROT();
    }

    // ---- block 7: (13,14,2,64)  32->64, 16x16 -> 8x8 ----
    conv3x3_k<32,64,16,2,false><<<NB,256,conv_smem(32,64,16)>>>(o, w + H_OFFS[13], h,  nullptr, ST(13));
    conv3x3_k<64,64, 8,1,true ><<<NB,256,conv_smem(64,64, 8)>>>(h, w + H_OFFS[14], h2, ST(13),  ST(14));
    elem_k<64,8,2,32><<<4096,256>>>(h2, ST(14), o, h);
    ROT();

    // ---- blocks 8,9: (15,16) (17,18), 64ch @8x8 ----
    for (int b = 0; b < 2; b++) {
        int la = 15 + 2*b, lb = la + 1;
        conv3x3_k<64,64,8,1,false><<<NB,256,conv_smem(64,64,8)>>>(o, w + H_OFFS[la], h,  nullptr, ST(la));
        conv3x3_k<64,64,8,1,true ><<<NB,256,conv_smem(64,64,8)>>>(h, w + H_OFFS[lb], h2, ST(la),  ST(lb));
        elem_k<64,8,1,64><<<4096,256>>>(h2, ST(lb), o, h);
        ROT();
    }

    // ---- pool + fc ----
    poolfc_k<<<NB,64>>>(o, Wfc, bfc, y);
#undef ROT
}

// round 2
// speedup vs baseline: 1.0407x; 1.0407x over previous
#include <cuda_runtime.h>
#include <cuda_bf16.h>
#include <cstdint>
#include <cstdio>

// ---------------------------------------------------------------------------
// Problem constants
// ---------------------------------------------------------------------------
#define NB 1024
static const int D_TOT = 267696;

// per-layer weight offsets (flat, in elements) and shapes
static const int H_OFFS[20] = {0,432,2736,5040,7344,9648,11952,14256,18864,28080,
                               37296,46512,55728,64944,83376,120240,157104,193968,230832,267696};

__constant__ int c_OFFS[20] = {0,432,2736,5040,7344,9648,11952,14256,18864,28080,
                               37296,46512,55728,64944,83376,120240,157104,193968,230832,267696};
__constant__ int c_CIN[19]  = {3,16,16,16,16,16,16,16,32,32,32,32,32,32,64,64,64,64,64};
__constant__ int c_COUT[19] = {16,16,16,16,16,16,16,32,32,32,32,32,32,64,64,64,64,64,64};

// ---------------------------------------------------------------------------
// Device scratch (no allocations allowed -> __device__ globals)
// ---------------------------------------------------------------------------
#define BUF_ELEMS (1024*16*32*32)   // 16.78M floats, largest activation
__device__ float  g_bufA[BUF_ELEMS];
__device__ float  g_bufB[BUF_ELEMS];
__device__ float  g_bufC[BUF_ELEMS];
__device__ float  g_w[267696];       // transposed per-layer: [cin][3x3][cout]
__device__ double g_stats[19*64*2];  // per layer, per channel: sum, sumsq

// ---------------------------------------------------------------------------
// Zero the BN stat accumulators (start of every graph replay)
// ---------------------------------------------------------------------------
__global__ void zstats_k(double* __restrict__ st) {
    int i = blockIdx.x * blockDim.x + threadIdx.x;
    if (i < 19*64*2) st[i] = 0.0;
}

// ---------------------------------------------------------------------------
// Reconstruct w_flat = origin + new_param @ P, then scatter into transposed
// per-layer layout [cin][ky*3+kx][cout] so conv blocks can stage weights with
// a contiguous copy and read them with LDS.128.
// ---------------------------------------------------------------------------
__global__ void wbuild_k(const float* __restrict__ ow, const float* __restrict__ P,
                         const float* __restrict__ npar, float* __restrict__ wt) {
    __shared__ float s_np[40];
    if (threadIdx.x < 40) s_np[threadIdx.x] = npar[threadIdx.x];
    __syncthreads();
    int d = blockIdx.x * blockDim.x + threadIdx.x;
    if (d >= D_TOT) return;
    float a = ow[d];
#pragma unroll
    for (int j = 0; j < 40; j++)
        a = fmaf(s_np[j], P[(size_t)j * D_TOT + d], a);
    // locate layer
    int l = 0;
    while (d >= c_OFFS[l+1]) l++;
    int r    = d - c_OFFS[l];
    int cin  = c_CIN[l];
    int cout = c_COUT[l];
    int oc   = r / (cin * 9);
    int rem  = r - oc * cin * 9;       // = ic*9 + k
    wt[c_OFFS[l] + rem * cout + oc] = a;
}

// ---------------------------------------------------------------------------
// Direct 3x3 conv, one image per block, 256 threads.
//   - input tile (padded) staged in smem, optional BN+ReLU applied on load
//   - weights staged in smem in [icr][k][oc] layout (LDS.128 reads)
//   - epilogue: write raw conv output + per-channel sum/sumsq block reduction
//     -> one double atomicAdd per (block, channel)
// ---------------------------------------------------------------------------
template<int CIN, int COUT, int HIN, int STRIDE, bool BN_IN>
__global__ void __launch_bounds__(256)
conv3x3_k(const float* __restrict__ in, const float* __restrict__ wt,
          float* __restrict__ out, const double* __restrict__ st_in,
          double* __restrict__ st_out)
{
    constexpr int HOUT   = HIN / STRIDE;
    constexpr int NPOS   = HOUT * HOUT;
    constexpr int PPT    = (NPOS >= 256) ? NPOS / 256 : 1;  // positions / thread
    constexpr int OCG    = (NPOS >= 256) ? 1 : 256 / NPOS;  // oc groups
    constexpr int OCPT   = COUT / OCG;                      // oc / thread
    constexpr int TIN    = HIN + 2;
    constexpr int INTILE = CIN * TIN * TIN;
    constexpr int WCHUNK = (COUT * CIN * 9 * 4 <= 40960) ? CIN : 16;
    constexpr int WTILE  = WCHUNK * 9 * COUT;

    extern __shared__ float sm[];
    float* s_in = sm;
    float* s_w  = sm + INTILE;
    float* s_sc = s_w + WTILE;
    float* s_sh = s_sc + CIN;

    const int tid = threadIdx.x;
    const int n   = blockIdx.x;

    if (BN_IN) {
        if (tid < CIN) {
            const double cnt = 1024.0 * HIN * HIN;
            double m = st_in[tid*2]   / cnt;
            double v = st_in[tid*2+1] / cnt - m * m;
            float rs = rsqrtf((float)v + 1e-5f);
            s_sc[tid] = rs;
            s_sh[tid] = (float)(-m) * rs;
        }
        __syncthreads();
    }

    // stage (padded) input tile, applying BN+ReLU if requested
    const float* inb = in + (size_t)n * CIN * HIN * HIN;
    for (int idx = tid; idx < INTILE; idx += 256) {
        int c  = idx / (TIN * TIN);
        int rr = idx - c * TIN * TIN;
        int iy = rr / TIN - 1;
        int ix = rr - (iy + 1) * TIN - 1;
        float v = 0.f;
        if ((unsigned)iy < (unsigned)HIN && (unsigned)ix < (unsigned)HIN) {
            v = __ldg(&inb[(c * HIN + iy) * HIN + ix]);
            if (BN_IN) v = fmaxf(fmaf(v, s_sc[c], s_sh[c]), 0.f);
        }
        s_in[idx] = v;
    }

    int pos0, ocbase;
    if (OCG == 1) { pos0 = tid;        ocbase = 0; }
    else          { pos0 = tid % NPOS; ocbase = (tid / NPOS) * OCPT; }

    float acc[OCPT][PPT];
#pragma unroll
    for (int o = 0; o < OCPT; o++)
#pragma unroll
        for (int i = 0; i < PPT; i++) acc[o][i] = 0.f;

    for (int ic0 = 0; ic0 < CIN; ic0 += WCHUNK) {
        __syncthreads();   // also covers initial s_in staging
        for (int idx = tid; idx < WTILE; idx += 256)
            s_w[idx] = wt[(size_t)ic0 * 9 * COUT + idx];
        __syncthreads();

#pragma unroll 1
        for (int icr = 0; icr < WCHUNK; icr++) {
            const int ic = ic0 + icr;
#pragma unroll
            for (int k = 0; k < 9; k++) {
                const int ky = k / 3, kx = k % 3;
                float iv[PPT];
#pragma unroll
                for (int i = 0; i < PPT; i++) {
                    int p  = pos0 + i * 256;
                    int oy = p / HOUT, ox = p % HOUT;
                    iv[i] = s_in[(ic * TIN + oy * STRIDE + ky) * TIN + ox * STRIDE + kx];
                }
                const float4* wp =
                    reinterpret_cast<const float4*>(&s_w[(icr * 9 + k) * COUT + ocbase]);
#pragma unroll
                for (int o4 = 0; o4 < OCPT / 4; o4++) {
                    float4 w4 = wp[o4];
#pragma unroll
                    for (int i = 0; i < PPT; i++) {
                        acc[o4*4+0][i] = fmaf(w4.x, iv[i], acc[o4*4+0][i]);
                        acc[o4*4+1][i] = fmaf(w4.y, iv[i], acc[o4*4+1][i]);
                        acc[o4*4+2][i] = fmaf(w4.z, iv[i], acc[o4*4+2][i]);
                        acc[o4*4+3][i] = fmaf(w4.w, iv[i], acc[o4*4+3][i]);
                    }
                }
            }
        }
    }

    // write raw conv output + per-thread partial stats
    const size_t ob = (size_t)n * COUT * NPOS;
    float psum[OCPT], psq[OCPT];
#pragma unroll
    for (int o = 0; o < OCPT; o++) { psum[o] = 0.f; psq[o] = 0.f; }
#pragma unroll
    for (int o = 0; o < OCPT; o++)
#pragma unroll
        for (int i = 0; i < PPT; i++) {
            int p   = pos0 + i * 256;
            float v = acc[o][i];
            out[ob + (size_t)(ocbase + o) * NPOS + p] = v;
            psum[o] += v;
            psq[o]   = fmaf(v, v, psq[o]);
        }

    // warp reduce (all lanes of a warp share the same oc set)
#pragma unroll
    for (int o = 0; o < OCPT; o++) {
#pragma unroll
        for (int s = 16; s; s >>= 1) {
            psum[o] += __shfl_down_sync(0xffffffffu, psum[o], s);
            psq[o]  += __shfl_down_sync(0xffffffffu, psq[o],  s);
        }
    }

    __syncthreads();                 // s_in no longer needed -> reuse as scratch
    float* s_red = sm;               // [8 warps][COUT][2]
    for (int idx = tid; idx < 8 * COUT * 2; idx += 256) s_red[idx] = 0.f;
    __syncthreads();
    const int lane = tid & 31, wid = tid >> 5;
    if (lane == 0) {
#pragma unroll
        for (int o = 0; o < OCPT; o++) {
            s_red[(wid * COUT + ocbase + o) * 2 + 0] = psum[o];
            s_red[(wid * COUT + ocbase + o) * 2 + 1] = psq[o];
        }
    }
    __syncthreads();
    if (tid < COUT) {
        float s = 0.f, q = 0.f;
#pragma unroll
        for (int w8 = 0; w8 < 8; w8++) {
            s += s_red[(w8 * COUT + tid) * 2 + 0];
            q += s_red[(w8 * COUT + tid) * 2 + 1];
        }
        atomicAdd(&st_out[tid * 2 + 0], (double)s);
        atomicAdd(&st_out[tid * 2 + 1], (double)q);
    }
}

// ---------------------------------------------------------------------------
// Residual epilogue: out = relu( bn(h) + shortcut(prev) )
//   MODE 0: no shortcut (layer 0)
//   MODE 1: identity shortcut
//   MODE 2: stride-2 subsample + channel zero-pad shortcut
// ---------------------------------------------------------------------------
template<int C, int H, int MODE, int CPREV>
__global__ void __launch_bounds__(256)
elem_k(const float* __restrict__ h, const double* __restrict__ st,
       const float* __restrict__ prev, float* __restrict__ out)
{
    __shared__ float s_sc[C], s_sh[C];
    if (threadIdx.x < C) {
        const double cnt = 1024.0 * H * H;
        double m = st[threadIdx.x*2]   / cnt;
        double v = st[threadIdx.x*2+1] / cnt - m * m;
        float rs = rsqrtf((float)v + 1e-5f);
        s_sc[threadIdx.x] = rs;
        s_sh[threadIdx.x] = (float)(-m) * rs;
    }
    __syncthreads();

    const int total = 1024 * C * H * H;
    for (int idx = blockIdx.x * blockDim.x + threadIdx.x; idx < total;
         idx += gridDim.x * blockDim.x) {
        int hw = idx % (H * H);
        int c  = (idx / (H * H)) % C;
        int n  = idx / (H * H * C);
        float v = fmaf(h[idx], s_sc[c], s_sh[c]);
        float s = 0.f;
        if (MODE == 1) {
            s = prev[idx];
        } else if (MODE == 2) {
            const int pc = c - (C - CPREV) / 2;
            if (pc >= 0 && pc < CPREV) {
                int y = hw / H, x = hw - y * H;
                s = prev[((size_t)n * CPREV + pc) * (4 * H * H) + (2*y) * (2*H) + 2*x];
            }
        }
        out[idx] = fmaxf(v + s, 0.f);
    }
}

// ---------------------------------------------------------------------------
// Global average pool (8x8) + FC 64->10
// ---------------------------------------------------------------------------
__global__ void __launch_bounds__(64)
poolfc_k(const float* __restrict__ in, const float* __restrict__ Wfc,
         const float* __restrict__ bfc, float* __restrict__ out)
{
    __shared__ float pooled[64];
    const int n = blockIdx.x, t = threadIdx.x;
    const float* p = in + (size_t)n * 64 * 64;
    float s = 0.f;
#pragma unroll
    for (int i = 0; i < 64; i++) s += p[t * 64 + i];
    pooled[t] = s * (1.f / 64.f);
    __syncthreads();
    if (t < 10) {
        float a = bfc[t];
#pragma unroll
        for (int c = 0; c < 64; c++) a = fmaf(Wfc[t * 64 + c], pooled[c], a);
        out[n * 10 + t] = a;
    }
}

// ---------------------------------------------------------------------------
// Host-side smem size helper (must match kernel layout)
// ---------------------------------------------------------------------------
static constexpr int conv_smem(int CIN, int COUT, int HIN) {
    int TIN = HIN + 2;
    int W   = (COUT * CIN * 9 * 4 <= 40960) ? CIN : 16;
    return (CIN * TIN * TIN + W * 9 * COUT + 2 * CIN) * 4;
}

extern "C" void kernel_launch(void* const* d_in, const int* in_sizes, int n_in,
                              void* d_out, int out_size)
{
    (void)in_sizes; (void)n_in; (void)out_size;
    const float* x   = (const float*)d_in[0];
    const float* ow  = (const float*)d_in[1];
    const float* P   = (const float*)d_in[2];
    const float* npar= (const float*)d_in[3];
    const float* Wfc = (const float*)d_in[4];
    const float* bfc = (const float*)d_in[5];
    float* y = (float*)d_out;

    float *A, *B, *C, *w; double* st;
    cudaGetSymbolAddress((void**)&A, g_bufA);
    cudaGetSymbolAddress((void**)&B, g_bufB);
    cudaGetSymbolAddress((void**)&C, g_bufC);
    cudaGetSymbolAddress((void**)&w, g_w);
    cudaGetSymbolAddress((void**)&st, g_stats);

    // opt in to >48KB dynamic smem (idempotent)
    cudaFuncSetAttribute(conv3x3_k< 3,16,32,1,false>, cudaFuncAttributeMaxDynamicSharedMemorySize, conv_smem( 3,16,32));
    cudaFuncSetAttribute(conv3x3_k<16,16,32,1,false>, cudaFuncAttributeMaxDynamicSharedMemorySize, conv_smem(16,16,32));
    cudaFuncSetAttribute(conv3x3_k<16,16,32,1,true >, cudaFuncAttributeMaxDynamicSharedMemorySize, conv_smem(16,16,32));
    cudaFuncSetAttribute(conv3x3_k<16,32,32,2,false>, cudaFuncAttributeMaxDynamicSharedMemorySize, conv_smem(16,32,32));
    cudaFuncSetAttribute(conv3x3_k<32,32,16,1,true >, cudaFuncAttributeMaxDynamicSharedMemorySize, conv_smem(32,32,16));
    cudaFuncSetAttribute(conv3x3_k<32,32,16,1,false>, cudaFuncAttributeMaxDynamicSharedMemorySize, conv_smem(32,32,16));
    cudaFuncSetAttribute(conv3x3_k<32,64,16,2,false>, cudaFuncAttributeMaxDynamicSharedMemorySize, conv_smem(32,64,16));
    cudaFuncSetAttribute(conv3x3_k<64,64, 8,1,true >, cudaFuncAttributeMaxDynamicSharedMemorySize, conv_smem(64,64, 8));
    cudaFuncSetAttribute(conv3x3_k<64,64, 8,1,false>, cudaFuncAttributeMaxDynamicSharedMemorySize, conv_smem(64,64, 8));

    auto ST = [&](int l) { return st + l * 128; };

    zstats_k<<<(19*64*2 + 255)/256, 256>>>(st);
    wbuild_k<<<(D_TOT + 255)/256, 256>>>(ow, P, npar, w);

    // ---- layer 0: out = relu(bn(conv0(x))) -> buffer B ----
    conv3x3_k<3,16,32,1,false><<<NB,256,conv_smem(3,16,32)>>>(x, w + H_OFFS[0], A, nullptr, ST(0));
    elem_k<16,32,0,16><<<4096,256>>>(A, ST(0), nullptr, B);

    float* o  = B;   // current activation
    float* h  = C;   // free
    float* h2 = A;   // free

    // a-conv: o -> h (raw, stats la); b-conv: bn(h)+relu -> h2 (stats lb);
    // elem: relu(bn(h2) + shortcut(o)) -> h; rotate (o,h,h2) = (h,h2,o)
#define ROT() { float* t = o; o = h; h = h2; h2 = t; }

    // ---- stage 1: blocks (1,2) (3,4) (5,6), 16ch @32x32 ----
    for (int b = 0; b < 3; b++) {
        int la = 1 + 2*b, lb = la + 1;
        conv3x3_k<16,16,32,1,false><<<NB,256,conv_smem(16,16,32)>>>(o, w + H_OFFS[la], h,  nullptr, ST(la));
        conv3x3_k<16,16,32,1,true ><<<NB,256,conv_smem(16,16,32)>>>(h, w + H_OFFS[lb], h2, ST(la),  ST(lb));
        elem_k<16,32,1,16><<<4096,256>>>(h2, ST(lb), o, h);
        ROT();
    }

    // ---- block 4: (7,8,2,32)  16->32, 32x32 -> 16x16 ----
    conv3x3_k<16,32,32,2,false><<<NB,256,conv_smem(16,32,32)>>>(o, w + H_OFFS[7], h,  nullptr, ST(7));
    conv3x3_k<32,32,16,1,true ><<<NB,256,conv_smem(32,32,16)>>>(h, w + H_OFFS[8], h2, ST(7),   ST(8));
    elem_k<32,16,2,16><<<4096,256>>>(h2, ST(8), o, h);
    ROT();

    // ---- blocks 5,6: (9,10) (11,12), 32ch @16x16 ----
    for (int b = 0; b < 2; b++) {
        int la = 9 + 2*b, lb = la + 1;
        conv3x3_k<32,32,16,1,false><<<NB,256,conv_smem(32,32,16)>>>(o, w + H_OFFS[la], h,  nullptr, ST(la));
        conv3x3_k<32,32,16,1,true ><<<NB,256,conv_smem(32,32,16)>>>(h, w + H_OFFS[lb], h2, ST(la),  ST(lb));
        elem_k<32,16,1,32><<<4096,256>>>(h2, ST(lb), o, h);
        ROT();
    }

    // ---- block 7: (13,14,2,64)  32->64, 16x16 -> 8x8 ----
    conv3x3_k<32,64,16,2,false><<<NB,256,conv_smem(32,64,16)>>>(o, w + H_OFFS[13], h,  nullptr, ST(13));
    conv3x3_k<64,64, 8,1,true ><<<NB,256,conv_smem(64,64, 8)>>>(h, w + H_OFFS[14], h2, ST(13),  ST(14));
    elem_k<64,8,2,32><<<4096,256>>>(h2, ST(14), o, h);
    ROT();

    // ---- blocks 8,9: (15,16) (17,18), 64ch @8x8 ----
    for (int b = 0; b < 2; b++) {
        int la = 15 + 2*b, lb = la + 1;
        conv3x3_k<64,64,8,1,false><<<NB,256,conv_smem(64,64,8)>>>(o, w + H_OFFS[la], h,  nullptr, ST(la));
        conv3x3_k<64,64,8,1,true ><<<NB,256,conv_smem(64,64,8)>>>(h, w + H_OFFS[lb], h2, ST(la),  ST(lb));
        elem_k<64,8,1,64><<<4096,256>>>(h2, ST(lb), o, h);
        ROT();
    }

    // ---- pool + fc ----
    poolfc_k<<<NB,64>>>(o, Wfc, bfc, y);
#undef ROT
}

// round 3
// speedup vs baseline: 1.0805x; 1.0383x over previous
#include <cuda_runtime.h>
#include <cuda_bf16.h>
#include <cstdint>
#include <cstdio>

// ---------------------------------------------------------------------------
// Problem constants
// ---------------------------------------------------------------------------
#define NB 1024
static const int D_TOT = 267696;

static const int H_OFFS[20] = {0,432,2736,5040,7344,9648,11952,14256,18864,28080,
                               37296,46512,55728,64944,83376,120240,157104,193968,230832,267696};

__constant__ int c_OFFS[20] = {0,432,2736,5040,7344,9648,11952,14256,18864,28080,
                               37296,46512,55728,64944,83376,120240,157104,193968,230832,267696};
__constant__ int c_CIN[19]  = {3,16,16,16,16,16,16,16,32,32,32,32,32,32,64,64,64,64,64};
__constant__ int c_COUT[19] = {16,16,16,16,16,16,16,32,32,32,32,32,32,64,64,64,64,64,64};

// ---------------------------------------------------------------------------
// Device scratch (no allocations allowed -> __device__ globals)
// ---------------------------------------------------------------------------
#define BUF_ELEMS (1024*16*32*32)
__device__ float  g_bufA[BUF_ELEMS];
__device__ float  g_bufB[BUF_ELEMS];
__device__ float  g_bufC[BUF_ELEMS];
__device__ float  g_w[267696];       // transposed per-layer: [cin][3x3][cout]
__device__ double g_stats[19*64*2];  // per layer, per channel: sum, sumsq

// ---------------------------------------------------------------------------
// Packed fp32x2 helpers (Blackwell FFMA2 — ptxas never auto-fuses these)
// ---------------------------------------------------------------------------
__device__ __forceinline__ unsigned long long pack2(float v) {
    unsigned long long r;
    unsigned u = __float_as_uint(v);
    asm("mov.b64 %0, {%1, %1};" : "=l"(r) : "r"(u));
    return r;
}
__device__ __forceinline__ void ffma2(unsigned long long& d,
                                      unsigned long long a, unsigned long long b) {
    asm("fma.rn.f32x2 %0, %1, %2, %0;" : "+l"(d) : "l"(a), "l"(b));
}
__device__ __forceinline__ void unpack2(unsigned long long a, float& lo, float& hi) {
    unsigned ulo, uhi;
    asm("mov.b64 {%0, %1}, %2;" : "=r"(ulo), "=r"(uhi) : "l"(a));
    lo = __uint_as_float(ulo);
    hi = __uint_as_float(uhi);
}

// ---------------------------------------------------------------------------
// Zero the BN stat accumulators (start of every graph replay)
// ---------------------------------------------------------------------------
__global__ void zstats_k(double* __restrict__ st) {
    int i = blockIdx.x * blockDim.x + threadIdx.x;
    if (i < 19*64*2) st[i] = 0.0;
}

// ---------------------------------------------------------------------------
// Reconstruct w_flat = origin + new_param @ P, scatter to [cin][k][cout]
// ---------------------------------------------------------------------------
__global__ void wbuild_k(const float* __restrict__ ow, const float* __restrict__ P,
                         const float* __restrict__ npar, float* __restrict__ wt) {
    __shared__ float s_np[40];
    if (threadIdx.x < 40) s_np[threadIdx.x] = npar[threadIdx.x];
    __syncthreads();
    int d = blockIdx.x * blockDim.x + threadIdx.x;
    if (d >= D_TOT) return;
    float a = ow[d];
#pragma unroll
    for (int j = 0; j < 40; j++)
        a = fmaf(s_np[j], P[(size_t)j * D_TOT + d], a);
    int l = 0;
    while (d >= c_OFFS[l+1]) l++;
    int r    = d - c_OFFS[l];
    int cin  = c_CIN[l];
    int cout = c_COUT[l];
    int oc   = r / (cin * 9);
    int rem  = r - oc * cin * 9;
    wt[c_OFFS[l] + rem * cout + oc] = a;
}

// ---------------------------------------------------------------------------
// Direct 3x3 conv, one image per block, 256 threads.
// Inner loop uses packed fp32x2 FMAs over adjacent output-channel pairs:
//   - weights read from smem as 64-bit pairs (LDS.64, broadcast)
//   - input scalar packed once per (k, position)
// ---------------------------------------------------------------------------
template<int CIN, int COUT, int HIN, int STRIDE, bool BN_IN>
__global__ void __launch_bounds__(256)
conv3x3_k(const float* __restrict__ in, const float* __restrict__ wt,
          float* __restrict__ out, const double* __restrict__ st_in,
          double* __restrict__ st_out)
{
    constexpr int HOUT   = HIN / STRIDE;
    constexpr int NPOS   = HOUT * HOUT;
    constexpr int PPT    = (NPOS >= 256) ? NPOS / 256 : 1;
    constexpr int OCG    = (NPOS >= 256) ? 1 : 256 / NPOS;
    constexpr int OCPT   = COUT / OCG;          // even for all instantiations
    constexpr int OCP2   = OCPT / 2;            // oc pairs per thread
    constexpr int TIN    = HIN + 2;
    constexpr int INTILE = CIN * TIN * TIN;
    constexpr int WCHUNK = (COUT * CIN * 9 * 4 <= 40960) ? CIN : 16;
    constexpr int WTILE  = WCHUNK * 9 * COUT;

    extern __shared__ float sm[];
    float* s_in = sm;
    float* s_w  = sm + INTILE;
    float* s_sc = s_w + WTILE;
    float* s_sh = s_sc + CIN;

    const int tid = threadIdx.x;
    const int n   = blockIdx.x;

    if (BN_IN) {
        if (tid < CIN) {
            const double cnt = 1024.0 * HIN * HIN;
            double m = st_in[tid*2]   / cnt;
            double v = st_in[tid*2+1] / cnt - m * m;
            float rs = rsqrtf((float)v + 1e-5f);
            s_sc[tid] = rs;
            s_sh[tid] = (float)(-m) * rs;
        }
        __syncthreads();
    }

    const float* inb = in + (size_t)n * CIN * HIN * HIN;
    for (int idx = tid; idx < INTILE; idx += 256) {
        int c  = idx / (TIN * TIN);
        int rr = idx - c * TIN * TIN;
        int iy = rr / TIN - 1;
        int ix = rr - (iy + 1) * TIN - 1;
        float v = 0.f;
        if ((unsigned)iy < (unsigned)HIN && (unsigned)ix < (unsigned)HIN) {
            v = __ldg(&inb[(c * HIN + iy) * HIN + ix]);
            if (BN_IN) v = fmaxf(fmaf(v, s_sc[c], s_sh[c]), 0.f);
        }
        s_in[idx] = v;
    }

    int pos0, ocbase;
    if (OCG == 1) { pos0 = tid;        ocbase = 0; }
    else          { pos0 = tid % NPOS; ocbase = (tid / NPOS) * OCPT; }

    unsigned long long acc[OCP2][PPT];
#pragma unroll
    for (int o = 0; o < OCP2; o++)
#pragma unroll
        for (int i = 0; i < PPT; i++) acc[o][i] = 0ULL;

    for (int ic0 = 0; ic0 < CIN; ic0 += WCHUNK) {
        __syncthreads();   // also covers initial s_in staging
        for (int idx = tid; idx < WTILE; idx += 256)
            s_w[idx] = wt[(size_t)ic0 * 9 * COUT + idx];
        __syncthreads();

#pragma unroll 1
        for (int icr = 0; icr < WCHUNK; icr++) {
            const int ic = ic0 + icr;
#pragma unroll
            for (int k = 0; k < 9; k++) {
                const int ky = k / 3, kx = k % 3;
                unsigned long long ivp[PPT];
#pragma unroll
                for (int i = 0; i < PPT; i++) {
                    int p  = pos0 + i * 256;
                    int oy = p / HOUT, ox = p % HOUT;
                    ivp[i] = pack2(
                        s_in[(ic * TIN + oy * STRIDE + ky) * TIN + ox * STRIDE + kx]);
                }
                const unsigned long long* wp =
                    reinterpret_cast<const unsigned long long*>(
                        &s_w[(icr * 9 + k) * COUT + ocbase]);
#pragma unroll
                for (int o = 0; o < OCP2; o++) {
                    unsigned long long w2 = wp[o];
#pragma unroll
                    for (int i = 0; i < PPT; i++)
                        ffma2(acc[o][i], w2, ivp[i]);
                }
            }
        }
    }

    // write raw conv output + per-thread partial stats
    const size_t ob = (size_t)n * COUT * NPOS;
    float psum[OCPT], psq[OCPT];
#pragma unroll
    for (int o = 0; o < OCPT; o++) { psum[o] = 0.f; psq[o] = 0.f; }
#pragma unroll
    for (int o = 0; o < OCP2; o++)
#pragma unroll
        for (int i = 0; i < PPT; i++) {
            int p = pos0 + i * 256;
            float v0, v1;
            unpack2(acc[o][i], v0, v1);
            out[ob + (size_t)(ocbase + 2*o + 0) * NPOS + p] = v0;
            out[ob + (size_t)(ocbase + 2*o + 1) * NPOS + p] = v1;
            psum[2*o + 0] += v0;  psq[2*o + 0] = fmaf(v0, v0, psq[2*o + 0]);
            psum[2*o + 1] += v1;  psq[2*o + 1] = fmaf(v1, v1, psq[2*o + 1]);
        }

#pragma unroll
    for (int o = 0; o < OCPT; o++) {
#pragma unroll
        for (int s = 16; s; s >>= 1) {
            psum[o] += __shfl_down_sync(0xffffffffu, psum[o], s);
            psq[o]  += __shfl_down_sync(0xffffffffu, psq[o],  s);
        }
    }

    __syncthreads();
    float* s_red = sm;               // [8 warps][COUT][2]
    for (int idx = tid; idx < 8 * COUT * 2; idx += 256) s_red[idx] = 0.f;
    __syncthreads();
    const int lane = tid & 31, wid = tid >> 5;
    if (lane == 0) {
#pragma unroll
        for (int o = 0; o < OCPT; o++) {
            s_red[(wid * COUT + ocbase + o) * 2 + 0] = psum[o];
            s_red[(wid * COUT + ocbase + o) * 2 + 1] = psq[o];
        }
    }
    __syncthreads();
    if (tid < COUT) {
        float s = 0.f, q = 0.f;
#pragma unroll
        for (int w8 = 0; w8 < 8; w8++) {
            s += s_red[(w8 * COUT + tid) * 2 + 0];
            q += s_red[(w8 * COUT + tid) * 2 + 1];
        }
        atomicAdd(&st_out[tid * 2 + 0], (double)s);
        atomicAdd(&st_out[tid * 2 + 1], (double)q);
    }
}

// ---------------------------------------------------------------------------
// Residual epilogue: out = relu( bn(h) + shortcut(prev) )
// ---------------------------------------------------------------------------
template<int C, int H, int MODE, int CPREV>
__global__ void __launch_bounds__(256)
elem_k(const float* __restrict__ h, const double* __restrict__ st,
       const float* __restrict__ prev, float* __restrict__ out)
{
    __shared__ float s_sc[C], s_sh[C];
    if (threadIdx.x < C) {
        const double cnt = 1024.0 * H * H;
        double m = st[threadIdx.x*2]   / cnt;
        double v = st[threadIdx.x*2+1] / cnt - m * m;
        float rs = rsqrtf((float)v + 1e-5f);
        s_sc[threadIdx.x] = rs;
        s_sh[threadIdx.x] = (float)(-m) * rs;
    }
    __syncthreads();

    const int total = 1024 * C * H * H;
    for (int idx = blockIdx.x * blockDim.x + threadIdx.x; idx < total;
         idx += gridDim.x * blockDim.x) {
        int hw = idx % (H * H);
        int c  = (idx / (H * H)) % C;
        int n  = idx / (H * H * C);
        float v = fmaf(h[idx], s_sc[c], s_sh[c]);
        float s = 0.f;
        if (MODE == 1) {
            s = prev[idx];
        } else if (MODE == 2) {
            const int pc = c - (C - CPREV) / 2;
            if (pc >= 0 && pc < CPREV) {
                int y = hw / H, x = hw - y * H;
                s = prev[((size_t)n * CPREV + pc) * (4 * H * H) + (2*y) * (2*H) + 2*x];
            }
        }
        out[idx] = fmaxf(v + s, 0.f);
    }
}

// ---------------------------------------------------------------------------
// Global average pool (8x8) + FC 64->10
// ---------------------------------------------------------------------------
__global__ void __launch_bounds__(64)
poolfc_k(const float* __restrict__ in, const float* __restrict__ Wfc,
         const float* __restrict__ bfc, float* __restrict__ out)
{
    __shared__ float pooled[64];
    const int n = blockIdx.x, t = threadIdx.x;
    const float* p = in + (size_t)n * 64 * 64;
    float s = 0.f;
#pragma unroll
    for (int i = 0; i < 64; i++) s += p[t * 64 + i];
    pooled[t] = s * (1.f / 64.f);
    __syncthreads();
    if (t < 10) {
        float a = bfc[t];
#pragma unroll
        for (int c = 0; c < 64; c++) a = fmaf(Wfc[t * 64 + c], pooled[c], a);
        out[n * 10 + t] = a;
    }
}

// ---------------------------------------------------------------------------
static constexpr int conv_smem(int CIN, int COUT, int HIN) {
    int TIN = HIN + 2;
    int W   = (COUT * CIN * 9 * 4 <= 40960) ? CIN : 16;
    return (CIN * TIN * TIN + W * 9 * COUT + 2 * CIN) * 4;
}

extern "C" void kernel_launch(void* const* d_in, const int* in_sizes, int n_in,
                              void* d_out, int out_size)
{
    (void)in_sizes; (void)n_in; (void)out_size;
    const float* x   = (const float*)d_in[0];
    const float* ow  = (const float*)d_in[1];
    const float* P   = (const float*)d_in[2];
    const float* npar= (const float*)d_in[3];
    const float* Wfc = (const float*)d_in[4];
    const float* bfc = (const float*)d_in[5];
    float* y = (float*)d_out;

    float *A, *B, *C, *w; double* st;
    cudaGetSymbolAddress((void**)&A, g_bufA);
    cudaGetSymbolAddress((void**)&B, g_bufB);
    cudaGetSymbolAddress((void**)&C, g_bufC);
    cudaGetSymbolAddress((void**)&w, g_w);
    cudaGetSymbolAddress((void**)&st, g_stats);

    cudaFuncSetAttribute(conv3x3_k< 3,16,32,1,false>, cudaFuncAttributeMaxDynamicSharedMemorySize, conv_smem( 3,16,32));
    cudaFuncSetAttribute(conv3x3_k<16,16,32,1,false>, cudaFuncAttributeMaxDynamicSharedMemorySize, conv_smem(16,16,32));
    cudaFuncSetAttribute(conv3x3_k<16,16,32,1,true >, cudaFuncAttributeMaxDynamicSharedMemorySize, conv_smem(16,16,32));
    cudaFuncSetAttribute(conv3x3_k<16,32,32,2,false>, cudaFuncAttributeMaxDynamicSharedMemorySize, conv_smem(16,32,32));
    cudaFuncSetAttribute(conv3x3_k<32,32,16,1,true >, cudaFuncAttributeMaxDynamicSharedMemorySize, conv_smem(32,32,16));
    cudaFuncSetAttribute(conv3x3_k<32,32,16,1,false>, cudaFuncAttributeMaxDynamicSharedMemorySize, conv_smem(32,32,16));
    cudaFuncSetAttribute(conv3x3_k<32,64,16,2,false>, cudaFuncAttributeMaxDynamicSharedMemorySize, conv_smem(32,64,16));
    cudaFuncSetAttribute(conv3x3_k<64,64, 8,1,true >, cudaFuncAttributeMaxDynamicSharedMemorySize, conv_smem(64,64, 8));
    cudaFuncSetAttribute(conv3x3_k<64,64, 8,1,false>, cudaFuncAttributeMaxDynamicSharedMemorySize, conv_smem(64,64, 8));

    auto ST = [&](int l) { return st + l * 128; };

    zstats_k<<<(19*64*2 + 255)/256, 256>>>(st);
    wbuild_k<<<(D_TOT + 255)/256, 256>>>(ow, P, npar, w);

    // ---- layer 0 ----
    conv3x3_k<3,16,32,1,false><<<NB,256,conv_smem(3,16,32)>>>(x, w + H_OFFS[0], A, nullptr, ST(0));
    elem_k<16,32,0,16><<<4096,256>>>(A, ST(0), nullptr, B);

    float* o  = B;
    float* h  = C;
    float* h2 = A;

#define ROT() { float* t = o; o = h; h = h2; h2 = t; }

    // ---- stage 1: 16ch @32x32 ----
    for (int b = 0; b < 3; b++) {
        int la = 1 + 2*b, lb = la + 1;
        conv3x3_k<16,16,32,1,false><<<NB,256,conv_smem(16,16,32)>>>(o, w + H_OFFS[la], h,  nullptr, ST(la));
        conv3x3_k<16,16,32,1,true ><<<NB,256,conv_smem(16,16,32)>>>(h, w + H_OFFS[lb], h2, ST(la),  ST(lb));
        elem_k<16,32,1,16><<<4096,256>>>(h2, ST(lb), o, h);
        ROT();
    }

    // ---- block 4: 16->32, stride 2 ----
    conv3x3_k<16,32,32,2,false><<<NB,256,conv_smem(16,32,32)>>>(o, w + H_OFFS[7], h,  nullptr, ST(7));
    conv3x3_k<32,32,16,1,true ><<<NB,256,conv_smem(32,32,16)>>>(h, w + H_OFFS[8], h2, ST(7),   ST(8));
    elem_k<32,16,2,16><<<4096,256>>>(h2, ST(8), o, h);
    ROT();

    // ---- blocks 5,6: 32ch @16x16 ----
    for (int b = 0; b < 2; b++) {
        int la = 9 + 2*b, lb = la + 1;
        conv3x3_k<32,32,16,1,false><<<NB,256,conv_smem(32,32,16)>>>(o, w + H_OFFS[la], h,  nullptr, ST(la));
        conv3x3_k<32,32,16,1,true ><<<NB,256,conv_smem(32,32,16)>>>(h, w + H_OFFS[lb], h2, ST(la),  ST(lb));
        elem_k<32,16,1,32><<<4096,256>>>(h2, ST(lb), o, h);
        ROT();
    }

    // ---- block 7: 32->64, stride 2 ----
    conv3x3_k<32,64,16,2,false><<<NB,256,conv_smem(32,64,16)>>>(o, w + H_OFFS[13], h,  nullptr, ST(13));
    conv3x3_k<64,64, 8,1,true ><<<NB,256,conv_smem(64,64, 8)>>>(h, w + H_OFFS[14], h2, ST(13),  ST(14));
    elem_k<64,8,2,32><<<4096,256>>>(h2, ST(14), o, h);
    ROT();

    // ---- blocks 8,9: 64ch @8x8 ----
    for (int b = 0; b < 2; b++) {
        int la = 15 + 2*b, lb = la + 1;
        conv3x3_k<64,64,8,1,false><<<NB,256,conv_smem(64,64,8)>>>(o, w + H_OFFS[la], h,  nullptr, ST(la));
        conv3x3_k<64,64,8,1,true ><<<NB,256,conv_smem(64,64,8)>>>(h, w + H_OFFS[lb], h2, ST(lb == 16 ? 15 : 17),  ST(lb));
        elem_k<64,8,1,64><<<4096,256>>>(h2, ST(lb), o, h);
        ROT();
    }

    // ---- pool + fc ----
    poolfc_k<<<NB,64>>>(o, Wfc, bfc, y);
#undef ROT
}